// round 15
// baseline (speedup 1.0000x reference)
#include <cuda_runtime.h>
#include <cuda_fp16.h>
#include <math.h>

#define NN 100000
#define NN_PAD 100352           // 98*1024, padded for guard-free scan
#define EE 1600000
#define NT 782                  // row tiles of 128
#define NNT (NT * 128)          // 100096, padded rows for guard-free tile loads
#define GRID_G 296              // persistent GEMM blocks (2 per SM)
#define G4 (EE / 4)             // 400000 int4 edge groups
#define FPB ((G4 + GRID_G - 1) / GRID_G)   // 1352 fill groups per block

// ---------------- scratch (device globals; no allocation allowed) ----------
__device__ int    g_cnt[NN_PAD];
__device__ int    g_off[NN];
__device__ int    g_base;
__device__ int    g_rank[EE];               // edge rank within destination
__device__ int    g_srcid[EE];
__device__ float  g_dinv[NN_PAD];
__device__ __half g_xh[(size_t)NNT * 128];  // x in fp16 (pad rows garbage, guarded)
__device__ __half g_hs[(size_t)NN * 128];   // hs = dinv[row] * (x@W1), fp16
__device__ float  g_hs2[NN * 2];
__device__ uint2  g_w1h[4096];              // W1 fp16 in m16n8k16 B-fragment order

// ---------------- helpers ---------------------------------------------------
__device__ __forceinline__ void mma_f16(float* d, const unsigned* a, unsigned b0, unsigned b1) {
    asm volatile("mma.sync.aligned.m16n8k16.row.col.f32.f16.f16.f32 "
                 "{%0,%1,%2,%3}, {%4,%5,%6,%7}, {%8,%9}, {%0,%1,%2,%3};\n"
                 : "+f"(d[0]), "+f"(d[1]), "+f"(d[2]), "+f"(d[3])
                 : "r"(a[0]), "r"(a[1]), "r"(a[2]), "r"(a[3]), "r"(b0), "r"(b1));
}
__device__ __forceinline__ void cpa16(unsigned dst, const void* src) {
    asm volatile("cp.async.cg.shared.global [%0], [%1], 16;\n" :: "r"(dst), "l"(src));
}
#define CPA_COMMIT() asm volatile("cp.async.commit_group;\n")
#define CPA_WAIT1()  asm volatile("cp.async.wait_group 1;\n")

// ---------------- fused: zero(g_cnt) + W1->fp16 fragments -------------------
__global__ void k_init(const float* __restrict__ W1) {
    int bid = blockIdx.x, tid = threadIdx.x;
    if (bid < 98) {
        int i = bid * 256 + tid;                       // int4 index, 25088 exact
        reinterpret_cast<int4*>(g_cnt)[i] = make_int4(0, 0, 0, 0);
        if (i == 0) g_base = 0;
    } else {
        int gid = (bid - 98) * 256 + tid;              // 4096 total
        int lane = gid & 31, rest = gid >> 5;
        int ks = rest & 7, t = rest >> 3;
        int n  = t * 8 + (lane >> 2);
        int k0 = ks * 16 + (lane & 3) * 2;
        __half2 b0 = __floats2half2_rn(W1[k0 * 128 + n],       W1[(k0 + 1) * 128 + n]);
        __half2 b1 = __floats2half2_rn(W1[(k0 + 8) * 128 + n], W1[(k0 + 9) * 128 + n]);
        g_w1h[gid] = make_uint2(*reinterpret_cast<unsigned*>(&b0),
                                *reinterpret_cast<unsigned*>(&b1));
    }
}

// ---------------- fused: count(+rank) interleaved with x->fp16 --------------
__global__ void k_cntcvt(const int* __restrict__ dst, const float* __restrict__ x) {
    int bid = blockIdx.x, tid = threadIdx.x;
    if (bid % 9 == 0) {
        int e4 = (bid / 9) * 256 + tid;
        if (e4 < G4) {
            int4 d = reinterpret_cast<const int4*>(dst)[e4];
            int4 r;
            r.x = atomicAdd(&g_cnt[d.x], 1);
            r.y = atomicAdd(&g_cnt[d.y], 1);
            r.z = atomicAdd(&g_cnt[d.z], 1);
            r.w = atomicAdd(&g_cnt[d.w], 1);
            reinterpret_cast<int4*>(g_rank)[e4] = r;
        }
    } else {
        int cb = bid - bid / 9 - 1;                    // cvtX block index 0..12499
        int i = cb * 256 + tid;                        // float4 index, 3200000 exact
        float4 v = __ldg(&reinterpret_cast<const float4*>(x)[i]);
        __half2 h0 = __floats2half2_rn(v.x, v.y);
        __half2 h1 = __floats2half2_rn(v.z, v.w);
        reinterpret_cast<uint2*>(g_xh)[i] =
            make_uint2(*reinterpret_cast<unsigned*>(&h0), *reinterpret_cast<unsigned*>(&h1));
    }
}

// ---------------- single-pass scan: counts -> offsets + dinv ----------------
__global__ void __launch_bounds__(256) k_scan() {
    __shared__ int wsum[8];
    __shared__ int sbase;
    int tid = threadIdx.x;
    int base = blockIdx.x * 1024 + tid * 4;
    int4 c = *reinterpret_cast<const int4*>(&g_cnt[base]);

    g_dinv[base + 0] = rsqrtf((float)(c.x + 1));
    g_dinv[base + 1] = rsqrtf((float)(c.y + 1));
    g_dinv[base + 2] = rsqrtf((float)(c.z + 1));
    g_dinv[base + 3] = rsqrtf((float)(c.w + 1));

    int s = c.x + c.y + c.z + c.w;
    int lane = tid & 31, w = tid >> 5;
    int incl = s;
#pragma unroll
    for (int o = 1; o < 32; o <<= 1) {
        int t = __shfl_up_sync(0xffffffffu, incl, o);
        if (lane >= o) incl += t;
    }
    if (lane == 31) wsum[w] = incl;
    __syncthreads();
    int wbase = 0, total = 0;
#pragma unroll
    for (int j = 0; j < 8; j++) { if (j < w) wbase += wsum[j]; total += wsum[j]; }
    if (tid == 0) sbase = atomicAdd(&g_base, total);
    __syncthreads();

    int ex = sbase + wbase + incl - s;
    if (base + 0 < NN) g_off[base + 0] = ex;
    if (base + 1 < NN) g_off[base + 1] = ex + c.x;
    if (base + 2 < NN) g_off[base + 2] = ex + c.x + c.y;
    if (base + 3 < NN) g_off[base + 3] = ex + c.x + c.y + c.z;
}

// ---------------- GEMM1 + fused CSR fill ------------------------------------
// Persistent, cp.async double-buffered fp16 MMA; each block also scatters its
// slice of the CSR srcid array inside the cp.async wait shadow.
#define SMEM_B_BYTES 32768
#define SMEM_A_BYTES 34816
#define SMEM_GEMM (SMEM_B_BYTES + 2 * SMEM_A_BYTES)   // 102400

__device__ __forceinline__ void loadA(unsigned sA_base, int buf, int tile, int tid) {
#pragma unroll
    for (int j = 0; j < 8; j++) {
        int c = tid + j * 256;            // chunk 0..2047 (16B each)
        int r = c >> 4, cc = c & 15;
        unsigned dst = sA_base + buf * SMEM_A_BYTES + r * 272 + cc * 16;
        const char* src = reinterpret_cast<const char*>(g_xh)
                        + ((size_t)tile * 128 + r) * 256 + cc * 16;
        cpa16(dst, src);
    }
}

__device__ __forceinline__ void fill_slice(const int* __restrict__ src,
                                           const int* __restrict__ dst,
                                           int s0, int s1, int tid) {
    for (int fi = s0 + tid; fi < s1; fi += 256) {
        int4 d = __ldg(&reinterpret_cast<const int4*>(dst)[fi]);
        int4 s = __ldg(&reinterpret_cast<const int4*>(src)[fi]);
        int4 r = reinterpret_cast<const int4*>(g_rank)[fi];
        g_srcid[__ldg(&g_off[d.x]) + r.x] = s.x;
        g_srcid[__ldg(&g_off[d.y]) + r.y] = s.y;
        g_srcid[__ldg(&g_off[d.z]) + r.z] = s.z;
        g_srcid[__ldg(&g_off[d.w]) + r.w] = s.w;
    }
}

__global__ void __launch_bounds__(256, 2) k_gemmfill(const int* __restrict__ src,
                                                     const int* __restrict__ dst) {
    extern __shared__ char smem[];
    unsigned sbase = (unsigned)__cvta_generic_to_shared(smem);
    unsigned sB_base = sbase;
    unsigned sA_base = sbase + SMEM_B_BYTES;
    uint2*    sB = reinterpret_cast<uint2*>(smem);
    unsigned* sAh = reinterpret_cast<unsigned*>(smem + SMEM_B_BYTES); // u32 view

    int tid = threadIdx.x;
    int w = tid >> 5, lane = tid & 31;
    int g = lane >> 2, tg = lane & 3;

    // fill work partition for this block
    int fBase = blockIdx.x * FPB;
    int fEnd  = fBase + FPB; if (fEnd > G4) fEnd = G4;
    int nIter = (NT - blockIdx.x + GRID_G - 1) / GRID_G;   // tiles for this block
    int perIter = (FPB + nIter - 1) / nIter;

    // prologue: B + A(tile0) in group0; A(tile1) in group1
#pragma unroll
    for (int j = 0; j < 8; j++) {
        int c = tid + j * 256;
        cpa16(sB_base + c * 16, reinterpret_cast<const char*>(g_w1h) + c * 16);
    }
    loadA(sA_base, 0, blockIdx.x, tid);
    CPA_COMMIT();
    if (blockIdx.x + GRID_G < NT) loadA(sA_base, 1, blockIdx.x + GRID_G, tid);
    CPA_COMMIT();
    CPA_WAIT1();
    __syncthreads();

    __half2* hs2p = reinterpret_cast<__half2*>(g_hs);
    int j = 0;
    for (int t = blockIdx.x; t < NT; t += GRID_G, j++) {
        const unsigned* sA = sAh + (j & 1) * (SMEM_A_BYTES / 4);

        float acc[16][4];
#pragma unroll
        for (int q = 0; q < 16; q++)
#pragma unroll
            for (int i = 0; i < 4; i++) acc[q][i] = 0.f;

        int r0 = w * 16 + g;
#pragma unroll
        for (int ks = 0; ks < 8; ks++) {
            int kw = ks * 8 + tg;
            unsigned a[4];
            a[0] = sA[r0 * 68 + kw];
            a[1] = sA[(r0 + 8) * 68 + kw];
            a[2] = sA[r0 * 68 + kw + 4];
            a[3] = sA[(r0 + 8) * 68 + kw + 4];
#pragma unroll
            for (int q = 0; q < 16; q++) {
                uint2 B = sB[(q * 8 + ks) * 32 + lane];
                mma_f16(acc[q], a, B.x, B.y);
            }
        }

        int gr0 = t * 128 + r0;
        int gr1 = gr0 + 8;
        float dv0 = g_dinv[gr0];              // gr < NNT < NN_PAD: safe
        float dv1 = g_dinv[gr1];
#pragma unroll
        for (int q = 0; q < 16; q++) {
            int col = q * 8 + tg * 2;
            if (gr0 < NN)
                hs2p[((size_t)gr0 * 128 + col) >> 1] =
                    __floats2half2_rn(acc[q][0] * dv0, acc[q][1] * dv0);
            if (gr1 < NN)
                hs2p[((size_t)gr1 * 128 + col) >> 1] =
                    __floats2half2_rn(acc[q][2] * dv1, acc[q][3] * dv1);
        }

        __syncthreads();                       // everyone done reading buf j&1
        int t2 = t + 2 * GRID_G;
        if (t2 < NT) loadA(sA_base, j & 1, t2, tid);
        CPA_COMMIT();

        // fill slice j in the cp.async wait shadow
        {
            int s0 = fBase + j * perIter;
            int s1 = s0 + perIter; if (s1 > fEnd) s1 = fEnd;
            if (s0 < s1) fill_slice(src, dst, s0, s1, tid);
        }

        if (t + GRID_G < NT) {
            CPA_WAIT1();
            __syncthreads();
        }
    }
}

// ---------------- Layer-1 aggregation + ReLU + GEMM2, warp per node --------
// hs is pre-scaled: acc = hs[n] + sum_nbr hs[s];  a = relu(dn*acc + b1)
__global__ void __launch_bounds__(256) k_agg1(const float* __restrict__ b1,
                                              const float* __restrict__ W2) {
    int gw = (blockIdx.x * 256 + threadIdx.x) >> 5;
    if (gw >= NN) return;
    int lane = threadIdx.x & 31;

    const uint2* hsv = reinterpret_cast<const uint2*>(g_hs);
    float dn = g_dinv[gw];

    uint2 raw = hsv[(size_t)gw * 32 + lane];                  // self loop (pre-scaled)
    float2 fa = __half22float2(*reinterpret_cast<__half2*>(&raw.x));
    float2 fb = __half22float2(*reinterpret_cast<__half2*>(&raw.y));
    float ax = fa.x, ay = fa.y, az = fb.x, aw = fb.y;

    int start = g_off[gw], len = g_cnt[gw];
    int i = 0;
    for (; i + 8 <= len; i += 8) {             // 8 independent gathers in flight
        int   s[8];
        uint2 r[8];
#pragma unroll
        for (int k = 0; k < 8; k++) s[k] = __ldg(&g_srcid[start + i + k]);
#pragma unroll
        for (int k = 0; k < 8; k++) r[k] = hsv[(size_t)s[k] * 32 + lane];
#pragma unroll
        for (int k = 0; k < 8; k++) {
            float2 va = __half22float2(*reinterpret_cast<__half2*>(&r[k].x));
            float2 vb = __half22float2(*reinterpret_cast<__half2*>(&r[k].y));
            ax += va.x; ay += va.y; az += vb.x; aw += vb.y;
        }
    }
    for (; i < len; i++) {
        int s0 = __ldg(&g_srcid[start + i]);
        uint2 r0 = hsv[(size_t)s0 * 32 + lane];
        float2 va0 = __half22float2(*reinterpret_cast<__half2*>(&r0.x));
        float2 vb0 = __half22float2(*reinterpret_cast<__half2*>(&r0.y));
        ax += va0.x; ay += va0.y; az += vb0.x; aw += vb0.y;
    }

    float4 bb = __ldg(reinterpret_cast<const float4*>(b1) + lane);
    float a0 = fmaxf(fmaf(dn, ax, bb.x), 0.f);
    float a1 = fmaxf(fmaf(dn, ay, bb.y), 0.f);
    float a2 = fmaxf(fmaf(dn, az, bb.z), 0.f);
    float a3 = fmaxf(fmaf(dn, aw, bb.w), 0.f);

    float4 wA = __ldg(reinterpret_cast<const float4*>(W2) + lane * 2);
    float4 wB = __ldg(reinterpret_cast<const float4*>(W2) + lane * 2 + 1);
    float p0 = a0 * wA.x + a1 * wA.z + a2 * wB.x + a3 * wB.z;
    float p1 = a0 * wA.y + a1 * wA.w + a2 * wB.y + a3 * wB.w;

#pragma unroll
    for (int o = 16; o; o >>= 1) {
        p0 += __shfl_xor_sync(0xffffffffu, p0, o);
        p1 += __shfl_xor_sync(0xffffffffu, p1, o);
    }
    if (lane == 0) {
        g_hs2[2 * gw]     = p0 * dn;
        g_hs2[2 * gw + 1] = p1 * dn;
    }
}

// ---------------- Layer-2 aggregation + bias + log_softmax ------------------
__global__ void __launch_bounds__(256) k_agg2(const float* __restrict__ b2,
                                              float* __restrict__ out) {
    int gw = (blockIdx.x * 256 + threadIdx.x) >> 5;
    if (gw >= NN) return;
    int lane = threadIdx.x & 31;

    int start = g_off[gw], len = g_cnt[gw];
    float s0 = 0.f, s1 = 0.f;
    const float2* h2 = reinterpret_cast<const float2*>(g_hs2);
    for (int i = lane; i < len; i += 32) {
        int s = __ldg(&g_srcid[start + i]);
        float2 v = h2[s];
        s0 += v.x; s1 += v.y;
    }
#pragma unroll
    for (int o = 16; o; o >>= 1) {
        s0 += __shfl_xor_sync(0xffffffffu, s0, o);
        s1 += __shfl_xor_sync(0xffffffffu, s1, o);
    }
    if (lane == 0) {
        float2 self = h2[gw];
        float dn = g_dinv[gw];
        float o0 = fmaf(dn, s0 + self.x, b2[0]);
        float o1 = fmaf(dn, s1 + self.y, b2[1]);
        float m  = fmaxf(o0, o1);
        float lse = m + logf(expf(o0 - m) + expf(o1 - m));
        out[2 * gw]     = o0 - lse;
        out[2 * gw + 1] = o1 - lse;
    }
}

// ---------------- launch (gemm+fill at profiled index 3) --------------------
extern "C" void kernel_launch(void* const* d_in, const int* in_sizes, int n_in,
                              void* d_out, int out_size) {
    (void)in_sizes; (void)n_in; (void)out_size;
    const float* x  = (const float*)d_in[0];
    const int*   ei = (const int*)  d_in[1];
    const float* W1 = (const float*)d_in[2];
    const float* b1 = (const float*)d_in[3];
    const float* W2 = (const float*)d_in[4];
    const float* b2 = (const float*)d_in[5];
    const int* src = ei;
    const int* dst = ei + EE;
    float* out = (float*)d_out;

    static bool attr_set = false;
    if (!attr_set) {
        cudaFuncSetAttribute(k_gemmfill, cudaFuncAttributeMaxDynamicSharedMemorySize, SMEM_GEMM);
        attr_set = true;
    }

    k_init    <<<114, 256>>>(W1);                        // 0: zero + cvtW
    k_cntcvt  <<<14063, 256>>>(dst, x);                  // 1: count + cvtX fused
    k_scan    <<<NN_PAD / 1024, 256>>>();                // 2
    k_gemmfill<<<GRID_G, 256, SMEM_GEMM>>>(src, dst);    // 3 <- profiled (gemm+fill)
    k_agg1    <<<(NN * 32 + 255) / 256, 256>>>(b1, W2);  // 4
    k_agg2    <<<(NN * 32 + 255) / 256, 256>>>(b2, out); // 5
}

// round 17
// speedup vs baseline: 1.0901x; 1.0901x over previous
#include <cuda_runtime.h>
#include <cuda_fp16.h>
#include <math.h>

#define NN 100000
#define NN_PAD 100352           // 98*1024, padded for guard-free scan
#define EE 1600000
#define NT 782                  // row tiles of 128
#define NNT (NT * 128)          // 100096, padded rows for guard-free tile loads
#define GRID_G 296              // persistent GEMM blocks (2 per SM)
#define G4 (EE / 4)             // 400000 int4 edge groups

// ---------------- scratch (device globals; no allocation allowed) ----------
__device__ int    g_cnt[NN_PAD];
__device__ int    g_off[NN];
__device__ int    g_base;
__device__ int    g_rank[EE];               // edge rank within destination
__device__ int    g_srcid[EE];
__device__ float  g_dinv[NN_PAD];
__device__ __half g_xh[(size_t)NNT * 128];  // x in fp16 (pad rows garbage, guarded)
__device__ __half g_hs[(size_t)NN * 128];   // hs = dinv[row] * (x@W1), fp16
__device__ float  g_hs2[NN * 2];
__device__ uint2  g_w1h[4096];              // W1 fp16 in m16n8k16 B-fragment order

// ---------------- helpers ---------------------------------------------------
__device__ __forceinline__ void mma_f16(float* d, const unsigned* a, unsigned b0, unsigned b1) {
    asm volatile("mma.sync.aligned.m16n8k16.row.col.f32.f16.f16.f32 "
                 "{%0,%1,%2,%3}, {%4,%5,%6,%7}, {%8,%9}, {%0,%1,%2,%3};\n"
                 : "+f"(d[0]), "+f"(d[1]), "+f"(d[2]), "+f"(d[3])
                 : "r"(a[0]), "r"(a[1]), "r"(a[2]), "r"(a[3]), "r"(b0), "r"(b1));
}
__device__ __forceinline__ void cpa16(unsigned dst, const void* src) {
    asm volatile("cp.async.cg.shared.global [%0], [%1], 16;\n" :: "r"(dst), "l"(src));
}
#define CPA_COMMIT() asm volatile("cp.async.commit_group;\n")
#define CPA_WAIT1()  asm volatile("cp.async.wait_group 1;\n")

// L1-bypassing (L2-cached) gathers for large random-access arrays
__device__ __forceinline__ uint2 ldcg_u2(const uint2* p) {
    uint2 v;
    asm volatile("ld.global.cg.v2.u32 {%0,%1}, [%2];" : "=r"(v.x), "=r"(v.y) : "l"(p));
    return v;
}
__device__ __forceinline__ float2 ldcg_f2(const float2* p) {
    float2 v;
    asm volatile("ld.global.cg.v2.f32 {%0,%1}, [%2];" : "=f"(v.x), "=f"(v.y) : "l"(p));
    return v;
}

// ---------------- fused: zero(g_cnt) + W1->fp16 fragments -------------------
__global__ void k_init(const float* __restrict__ W1) {
    int bid = blockIdx.x, tid = threadIdx.x;
    if (bid < 98) {
        int i = bid * 256 + tid;                       // int4 index, 25088 exact
        reinterpret_cast<int4*>(g_cnt)[i] = make_int4(0, 0, 0, 0);
        if (i == 0) g_base = 0;
    } else {
        int gid = (bid - 98) * 256 + tid;              // 4096 total
        int lane = gid & 31, rest = gid >> 5;
        int ks = rest & 7, t = rest >> 3;
        int n  = t * 8 + (lane >> 2);
        int k0 = ks * 16 + (lane & 3) * 2;
        __half2 b0 = __floats2half2_rn(W1[k0 * 128 + n],       W1[(k0 + 1) * 128 + n]);
        __half2 b1 = __floats2half2_rn(W1[(k0 + 8) * 128 + n], W1[(k0 + 9) * 128 + n]);
        g_w1h[gid] = make_uint2(*reinterpret_cast<unsigned*>(&b0),
                                *reinterpret_cast<unsigned*>(&b1));
    }
}

// ---------------- fused: count(+rank) interleaved with x->fp16 --------------
__global__ void k_cntcvt(const int* __restrict__ dst, const float* __restrict__ x) {
    int bid = blockIdx.x, tid = threadIdx.x;
    if (bid % 9 == 0) {
        int e4 = (bid / 9) * 256 + tid;
        if (e4 < G4) {
            int4 d = reinterpret_cast<const int4*>(dst)[e4];
            int4 r;
            r.x = atomicAdd(&g_cnt[d.x], 1);
            r.y = atomicAdd(&g_cnt[d.y], 1);
            r.z = atomicAdd(&g_cnt[d.z], 1);
            r.w = atomicAdd(&g_cnt[d.w], 1);
            reinterpret_cast<int4*>(g_rank)[e4] = r;
        }
    } else {
        int cb = bid - bid / 9 - 1;                    // cvtX block index 0..12499
        int i = cb * 256 + tid;                        // float4 index, 3200000 exact
        float4 v = __ldg(&reinterpret_cast<const float4*>(x)[i]);
        __half2 h0 = __floats2half2_rn(v.x, v.y);
        __half2 h1 = __floats2half2_rn(v.z, v.w);
        reinterpret_cast<uint2*>(g_xh)[i] =
            make_uint2(*reinterpret_cast<unsigned*>(&h0), *reinterpret_cast<unsigned*>(&h1));
    }
}

// ---------------- single-pass scan: counts -> offsets + dinv ----------------
__global__ void __launch_bounds__(256) k_scan() {
    __shared__ int wsum[8];
    __shared__ int sbase;
    int tid = threadIdx.x;
    int base = blockIdx.x * 1024 + tid * 4;
    int4 c = *reinterpret_cast<const int4*>(&g_cnt[base]);

    g_dinv[base + 0] = rsqrtf((float)(c.x + 1));
    g_dinv[base + 1] = rsqrtf((float)(c.y + 1));
    g_dinv[base + 2] = rsqrtf((float)(c.z + 1));
    g_dinv[base + 3] = rsqrtf((float)(c.w + 1));

    int s = c.x + c.y + c.z + c.w;
    int lane = tid & 31, w = tid >> 5;
    int incl = s;
#pragma unroll
    for (int o = 1; o < 32; o <<= 1) {
        int t = __shfl_up_sync(0xffffffffu, incl, o);
        if (lane >= o) incl += t;
    }
    if (lane == 31) wsum[w] = incl;
    __syncthreads();
    int wbase = 0, total = 0;
#pragma unroll
    for (int j = 0; j < 8; j++) { if (j < w) wbase += wsum[j]; total += wsum[j]; }
    if (tid == 0) sbase = atomicAdd(&g_base, total);
    __syncthreads();

    int ex = sbase + wbase + incl - s;
    if (base + 0 < NN) g_off[base + 0] = ex;
    if (base + 1 < NN) g_off[base + 1] = ex + c.x;
    if (base + 2 < NN) g_off[base + 2] = ex + c.x + c.y;
    if (base + 3 < NN) g_off[base + 3] = ex + c.x + c.y + c.z;
}

// ---------------- fill: atomic-free CSR scatter, 4 edges/thread --------------
__global__ void k_fill(const int* __restrict__ src, const int* __restrict__ dst) {
    int e4 = blockIdx.x * blockDim.x + threadIdx.x;
    if (e4 < G4) {
        int4 d = reinterpret_cast<const int4*>(dst)[e4];
        int4 s = reinterpret_cast<const int4*>(src)[e4];
        int4 r = reinterpret_cast<const int4*>(g_rank)[e4];
        g_srcid[__ldg(&g_off[d.x]) + r.x] = s.x;
        g_srcid[__ldg(&g_off[d.y]) + r.y] = s.y;
        g_srcid[__ldg(&g_off[d.z]) + r.z] = s.z;
        g_srcid[__ldg(&g_off[d.w]) + r.w] = s.w;
    }
}

// ---------------- GEMM1: persistent, cp.async double-buffered fp16 MMA ------
#define SMEM_B_BYTES 32768
#define SMEM_A_BYTES 34816
#define SMEM_GEMM (SMEM_B_BYTES + 2 * SMEM_A_BYTES)   // 102400

__device__ __forceinline__ void loadA(unsigned sA_base, int buf, int tile, int tid) {
#pragma unroll
    for (int j = 0; j < 8; j++) {
        int c = tid + j * 256;            // chunk 0..2047 (16B each)
        int r = c >> 4, cc = c & 15;
        unsigned dst = sA_base + buf * SMEM_A_BYTES + r * 272 + cc * 16;
        const char* src = reinterpret_cast<const char*>(g_xh)
                        + ((size_t)tile * 128 + r) * 256 + cc * 16;
        cpa16(dst, src);
    }
}

__global__ void __launch_bounds__(256) k_gemm1h() {
    extern __shared__ char smem[];
    unsigned sbase = (unsigned)__cvta_generic_to_shared(smem);
    unsigned sB_base = sbase;
    unsigned sA_base = sbase + SMEM_B_BYTES;
    uint2*    sB = reinterpret_cast<uint2*>(smem);
    unsigned* sAh = reinterpret_cast<unsigned*>(smem + SMEM_B_BYTES); // u32 view

    int tid = threadIdx.x;
    int w = tid >> 5, lane = tid & 31;
    int g = lane >> 2, tg = lane & 3;

    // prologue: B + A(tile0) in group0; A(tile1) in group1
#pragma unroll
    for (int j = 0; j < 8; j++) {
        int c = tid + j * 256;
        cpa16(sB_base + c * 16, reinterpret_cast<const char*>(g_w1h) + c * 16);
    }
    loadA(sA_base, 0, blockIdx.x, tid);
    CPA_COMMIT();
    if (blockIdx.x + GRID_G < NT) loadA(sA_base, 1, blockIdx.x + GRID_G, tid);
    CPA_COMMIT();
    CPA_WAIT1();
    __syncthreads();

    __half2* hs2p = reinterpret_cast<__half2*>(g_hs);
    int j = 0;
    for (int t = blockIdx.x; t < NT; t += GRID_G, j++) {
        const unsigned* sA = sAh + (j & 1) * (SMEM_A_BYTES / 4);

        float acc[16][4];
#pragma unroll
        for (int q = 0; q < 16; q++)
#pragma unroll
            for (int i = 0; i < 4; i++) acc[q][i] = 0.f;

        int r0 = w * 16 + g;
#pragma unroll
        for (int ks = 0; ks < 8; ks++) {
            int kw = ks * 8 + tg;
            unsigned a[4];
            a[0] = sA[r0 * 68 + kw];
            a[1] = sA[(r0 + 8) * 68 + kw];
            a[2] = sA[r0 * 68 + kw + 4];
            a[3] = sA[(r0 + 8) * 68 + kw + 4];
#pragma unroll
            for (int q = 0; q < 16; q++) {
                uint2 B = sB[(q * 8 + ks) * 32 + lane];
                mma_f16(acc[q], a, B.x, B.y);
            }
        }

        int gr0 = t * 128 + r0;
        int gr1 = gr0 + 8;
        float dv0 = g_dinv[gr0];              // gr < NNT < NN_PAD: safe
        float dv1 = g_dinv[gr1];
#pragma unroll
        for (int q = 0; q < 16; q++) {
            int col = q * 8 + tg * 2;
            if (gr0 < NN)
                hs2p[((size_t)gr0 * 128 + col) >> 1] =
                    __floats2half2_rn(acc[q][0] * dv0, acc[q][1] * dv0);
            if (gr1 < NN)
                hs2p[((size_t)gr1 * 128 + col) >> 1] =
                    __floats2half2_rn(acc[q][2] * dv1, acc[q][3] * dv1);
        }

        __syncthreads();                       // everyone done reading buf j&1
        int t2 = t + 2 * GRID_G;
        if (t2 < NT) loadA(sA_base, j & 1, t2, tid);
        CPA_COMMIT();
        if (t + GRID_G < NT) {
            CPA_WAIT1();
            __syncthreads();
        }
    }
}

// ---------------- Layer-1 aggregation + ReLU + GEMM2, warp per node --------
// hs is pre-scaled: acc = hs[n] + sum_nbr hs[s];  a = relu(dn*acc + b1)
__global__ void __launch_bounds__(256) k_agg1(const float* __restrict__ b1,
                                              const float* __restrict__ W2) {
    int gw = (blockIdx.x * 256 + threadIdx.x) >> 5;
    if (gw >= NN) return;
    int lane = threadIdx.x & 31;

    const uint2* hsv = reinterpret_cast<const uint2*>(g_hs);
    float dn = g_dinv[gw];

    uint2 raw = ldcg_u2(&hsv[(size_t)gw * 32 + lane]);        // self loop (pre-scaled)
    float2 fa = __half22float2(*reinterpret_cast<__half2*>(&raw.x));
    float2 fb = __half22float2(*reinterpret_cast<__half2*>(&raw.y));
    float ax = fa.x, ay = fa.y, az = fb.x, aw = fb.y;

    int start = g_off[gw], len = g_cnt[gw];
    int i = 0;
    for (; i + 8 <= len; i += 8) {             // 8 independent gathers in flight
        int   s[8];
        uint2 r[8];
#pragma unroll
        for (int k = 0; k < 8; k++) s[k] = __ldg(&g_srcid[start + i + k]);
#pragma unroll
        for (int k = 0; k < 8; k++) r[k] = ldcg_u2(&hsv[(size_t)s[k] * 32 + lane]);
#pragma unroll
        for (int k = 0; k < 8; k++) {
            float2 va = __half22float2(*reinterpret_cast<__half2*>(&r[k].x));
            float2 vb = __half22float2(*reinterpret_cast<__half2*>(&r[k].y));
            ax += va.x; ay += va.y; az += vb.x; aw += vb.y;
        }
    }
    for (; i < len; i++) {
        int s0 = __ldg(&g_srcid[start + i]);
        uint2 r0 = ldcg_u2(&hsv[(size_t)s0 * 32 + lane]);
        float2 va0 = __half22float2(*reinterpret_cast<__half2*>(&r0.x));
        float2 vb0 = __half22float2(*reinterpret_cast<__half2*>(&r0.y));
        ax += va0.x; ay += va0.y; az += vb0.x; aw += vb0.y;
    }

    float4 bb = __ldg(reinterpret_cast<const float4*>(b1) + lane);
    float a0 = fmaxf(fmaf(dn, ax, bb.x), 0.f);
    float a1 = fmaxf(fmaf(dn, ay, bb.y), 0.f);
    float a2 = fmaxf(fmaf(dn, az, bb.z), 0.f);
    float a3 = fmaxf(fmaf(dn, aw, bb.w), 0.f);

    float4 wA = __ldg(reinterpret_cast<const float4*>(W2) + lane * 2);
    float4 wB = __ldg(reinterpret_cast<const float4*>(W2) + lane * 2 + 1);
    float p0 = a0 * wA.x + a1 * wA.z + a2 * wB.x + a3 * wB.z;
    float p1 = a0 * wA.y + a1 * wA.w + a2 * wB.y + a3 * wB.w;

#pragma unroll
    for (int o = 16; o; o >>= 1) {
        p0 += __shfl_xor_sync(0xffffffffu, p0, o);
        p1 += __shfl_xor_sync(0xffffffffu, p1, o);
    }
    if (lane == 0) {
        g_hs2[2 * gw]     = p0 * dn;
        g_hs2[2 * gw + 1] = p1 * dn;
    }
}

// ---------------- Layer-2 aggregation + bias + log_softmax ------------------
__global__ void __launch_bounds__(256) k_agg2(const float* __restrict__ b2,
                                              float* __restrict__ out) {
    int gw = (blockIdx.x * 256 + threadIdx.x) >> 5;
    if (gw >= NN) return;
    int lane = threadIdx.x & 31;

    int start = g_off[gw], len = g_cnt[gw];
    float s0 = 0.f, s1 = 0.f;
    const float2* h2 = reinterpret_cast<const float2*>(g_hs2);
    for (int i = lane; i < len; i += 32) {
        int s = __ldg(&g_srcid[start + i]);
        float2 v = ldcg_f2(&h2[s]);
        s0 += v.x; s1 += v.y;
    }
#pragma unroll
    for (int o = 16; o; o >>= 1) {
        s0 += __shfl_xor_sync(0xffffffffu, s0, o);
        s1 += __shfl_xor_sync(0xffffffffu, s1, o);
    }
    if (lane == 0) {
        float2 self = h2[gw];
        float dn = g_dinv[gw];
        float o0 = fmaf(dn, s0 + self.x, b2[0]);
        float o1 = fmaf(dn, s1 + self.y, b2[1]);
        float m  = fmaxf(o0, o1);
        float lse = m + logf(expf(o0 - m) + expf(o1 - m));
        out[2 * gw]     = o0 - lse;
        out[2 * gw + 1] = o1 - lse;
    }
}

// ---------------- launch (serial; fill at profiled index 3) -----------------
extern "C" void kernel_launch(void* const* d_in, const int* in_sizes, int n_in,
                              void* d_out, int out_size) {
    (void)in_sizes; (void)n_in; (void)out_size;
    const float* x  = (const float*)d_in[0];
    const int*   ei = (const int*)  d_in[1];
    const float* W1 = (const float*)d_in[2];
    const float* b1 = (const float*)d_in[3];
    const float* W2 = (const float*)d_in[4];
    const float* b2 = (const float*)d_in[5];
    const int* src = ei;
    const int* dst = ei + EE;
    float* out = (float*)d_out;

    static bool attr_set = false;
    if (!attr_set) {
        cudaFuncSetAttribute(k_gemm1h, cudaFuncAttributeMaxDynamicSharedMemorySize, SMEM_GEMM);
        attr_set = true;
    }

    k_init  <<<114, 256>>>(W1);                         // 0: zero + cvtW
    k_cntcvt<<<14063, 256>>>(dst, x);                   // 1: count + cvtX fused
    k_scan  <<<NN_PAD / 1024, 256>>>();                 // 2
    k_fill  <<<(G4 + 255) / 256, 256>>>(src, dst);      // 3 <- profiled
    k_gemm1h<<<GRID_G, 256, SMEM_GEMM>>>();             // 4
    k_agg1  <<<(NN * 32 + 255) / 256, 256>>>(b1, W2);   // 5
    k_agg2  <<<(NN * 32 + 255) / 256, 256>>>(b2, out);  // 6
}